// round 12
// baseline (speedup 1.0000x reference)
#include <cuda_runtime.h>
#include <cuda_fp16.h>
#include <cuda_bf16.h>
#include <cstdint>

// ---------------------------------------------------------------------------
// BipartiteGConv, CSR + 3xTF32 tensor-core GEMMs.
// Base = R11 (139.3us best). R12 single delta: lhs stored/gathered as fp16
// (halves the dominant row_kernel gather traffic). rhs stays fp32.
// ---------------------------------------------------------------------------

#define N_IN_MAX  100000
#define N_OT_MAX  50000
#define E_MAX     1050000
#define SCAN_B    1024
#define READY_BIT 0x40000000
#define VAL_MASK  0x3FFFFFFF

__device__ float  g_rhs[N_IN_MAX * 64];
__device__ __half g_lhs[N_OT_MAX * 64];     // fp16 (R12 delta)
__device__ float  g_acc[N_IN_MAX * 64];
__device__ int    g_cnt[N_IN_MAX];
__device__ int    g_row_start[N_IN_MAX + 1];
__device__ int    g_cursor[N_IN_MAX];
__device__ int    g_part[128];
__device__ float2 g_edges[E_MAX];
__device__ float  g_Wcomb[64 * 64];
__device__ float  g_bfw[64];

// ---------------- zero cnt ----------------
__global__ void zero_cnt_kernel(int* __restrict__ cnt, int n) {
    int i = blockIdx.x * blockDim.x + threadIdx.x;
    if (i < n) cnt[i] = 0;
}

// ---------------- histogram ----------------
__global__ void hist_kernel(const int* __restrict__ rj, int* __restrict__ cnt, int E) {
    int e = blockIdx.x * blockDim.x + threadIdx.x;
    if (e < E) atomicAdd(cnt + __ldg(rj + e), 1);
}

// ---------------- fused single-pass scan (R11-proven) ----------------
__global__ void scan_fused_kernel(const int* __restrict__ cnt,
                                  int* __restrict__ row_start,
                                  int* __restrict__ cursor,
                                  int* __restrict__ part, int N, int E) {
    __shared__ int s[SCAN_B];
    __shared__ int prefix_sh;
    const int tid = threadIdx.x;
    const int b = blockIdx.x;
    const int i = b * SCAN_B + tid;

    int v = (i < N) ? cnt[i] : 0;
    s[tid] = v;
    __syncthreads();
    int x = v;
#pragma unroll
    for (int d = 1; d < SCAN_B; d <<= 1) {
        int t = (tid >= d) ? s[tid - d] : 0;
        __syncthreads();
        x += t;
        s[tid] = x;
        __syncthreads();
    }
    const int total = s[SCAN_B - 1];

    if (tid == 0) atomicExch(&part[b], total | READY_BIT);
    if (tid < 32) {
        int pre = 0;
        for (int p = b - 1 - tid; p >= 0; p -= 32) {
            int w;
            do { w = *(volatile int*)(part + p); } while (!(w & READY_BIT));
            pre += w & VAL_MASK;
        }
#pragma unroll
        for (int d = 16; d > 0; d >>= 1)
            pre += __shfl_xor_sync(0xffffffffu, pre, d);
        if (tid == 0) prefix_sh = pre;
    }
    __syncthreads();

    if (i < N) {
        int e = x - v + prefix_sh;
        row_start[i] = e;
        cursor[i] = e;
    }
    if (b == 0 && tid == 0) row_start[N] = E;
}

// ---------------- scatter (R11-proven ILP-4 + flag reset) ----------------
__global__ void scatter_kernel(const int* __restrict__ rj,
                               const int* __restrict__ lj,
                               const float* __restrict__ w,
                               int* __restrict__ cursor,
                               int* __restrict__ part,
                               float2* __restrict__ edges, int E) {
    if (blockIdx.x == 0 && threadIdx.x < 128) part[threadIdx.x] = 0;
    int base = blockIdx.x * (blockDim.x * 4) + threadIdx.x;
    int   r[4], l[4];
    float wv[4];
    bool  ok[4];
#pragma unroll
    for (int k = 0; k < 4; k++) {
        int e = base + k * 256;
        ok[k] = (e < E);
        if (ok[k]) {
            r[k]  = __ldg(rj + e);
            l[k]  = __ldg(lj + e);
            wv[k] = __ldg(w + e);
        }
    }
    int p[4];
#pragma unroll
    for (int k = 0; k < 4; k++)
        if (ok[k]) p[k] = atomicAdd(cursor + r[k], 1);
#pragma unroll
    for (int k = 0; k < 4; k++)
        if (ok[k]) edges[p[k]] = make_float2(__int_as_float(l[k]), wv[k]);
}

// ======================= tf32 mma helpers ===================================
__device__ __forceinline__ uint32_t cvt_tf32(float x) {
    uint32_t u;
    asm("cvt.rna.tf32.f32 %0, %1;" : "=r"(u) : "f"(x));
    return u;
}
__device__ __forceinline__ void split_tf32(float x, uint32_t& hi, uint32_t& lo) {
    hi = cvt_tf32(x);
    lo = cvt_tf32(x - __uint_as_float(hi));
}
__device__ __forceinline__ void mma8(float* c,
                                     uint32_t a0, uint32_t a1, uint32_t a2, uint32_t a3,
                                     uint32_t b0, uint32_t b1) {
    asm volatile(
        "mma.sync.aligned.m16n8k8.row.col.f32.tf32.tf32.f32 "
        "{%0,%1,%2,%3}, {%4,%5,%6,%7}, {%8,%9}, {%0,%1,%2,%3};"
        : "+f"(c[0]), "+f"(c[1]), "+f"(c[2]), "+f"(c[3])
        : "r"(a0), "r"(a1), "r"(a2), "r"(a3), "r"(b0), "r"(b1));
}

#define AST 68

__device__ __forceinline__ void stage_A(const float* __restrict__ A,
                                        int block_row, int M,
                                        float* sA, int tid) {
#pragma unroll
    for (int it = 0; it < 8; it++) {
        int i = tid + it * 128;
        int r = i >> 4, c4 = (i & 15) * 4;
        int gr = block_row + r;
        float4 v = (gr < M) ? *reinterpret_cast<const float4*>(A + (size_t)gr * 64 + c4)
                            : make_float4(0.f, 0.f, 0.f, 0.f);
        *reinterpret_cast<float4*>(sA + r * AST + c4) = v;
    }
}
__device__ __forceinline__ void stage_W(const float* __restrict__ W,
                                        float* sW, int tid) {
#pragma unroll
    for (int it = 0; it < 8; it++) {
        int i = tid + it * 128;
        int r = i >> 4, c4 = (i & 15) * 4;
        float4 w = *reinterpret_cast<const float4*>(W + r * 64 + c4);
        *reinterpret_cast<float4*>(sW + r * AST + c4) = w;
    }
}

__device__ __forceinline__ void tile_mma(const float* sA, const float* sW,
                                         int wr, int wc, int g, int tig,
                                         float cacc[2][4][4]) {
#pragma unroll
    for (int ks = 0; ks < 8; ks++) {
        const int kb = ks * 8;
        uint32_t ahi[2][4], alo[2][4];
#pragma unroll
        for (int mt = 0; mt < 2; mt++) {
            const int base = (wr + mt * 16 + g) * AST + kb + tig;
            split_tf32(sA[base],               ahi[mt][0], alo[mt][0]);
            split_tf32(sA[base + 8 * AST],     ahi[mt][1], alo[mt][1]);
            split_tf32(sA[base + 4],           ahi[mt][2], alo[mt][2]);
            split_tf32(sA[base + 8 * AST + 4], ahi[mt][3], alo[mt][3]);
        }
#pragma unroll
        for (int nt = 0; nt < 4; nt++) {
            const int nb = wc + nt * 8;
            float w0 = sW[(kb + tig) * AST + nb + g];
            float w1 = sW[(kb + tig + 4) * AST + nb + g];
            uint32_t bh0, bl0, bh1, bl1;
            split_tf32(w0, bh0, bl0);
            split_tf32(w1, bh1, bl1);
#pragma unroll
            for (int mt = 0; mt < 2; mt++) {
                mma8(cacc[mt][nt], ahi[mt][0], ahi[mt][1], ahi[mt][2], ahi[mt][3], bh0, bh1);
                mma8(cacc[mt][nt], ahi[mt][0], ahi[mt][1], ahi[mt][2], ahi[mt][3], bl0, bl1);
                mma8(cacc[mt][nt], alo[mt][0], alo[mt][1], alo[mt][2], alo[mt][3], bh0, bh1);
            }
        }
    }
}

// ============ gemm_both: rhs -> fp32, lhs -> fp16 (R12 delta in epilogue) ===
__global__ __launch_bounds__(128)
void gemm_both_tf32(const float* __restrict__ input,
                    const float* __restrict__ Wi,
                    const float* __restrict__ bi,
                    const float* __restrict__ other,
                    const float* __restrict__ Wo,
                    float* __restrict__ rhs,
                    __half* __restrict__ lhs,
                    int M_in, int M_ot, int blocks_in) {
    __shared__ float sA[64 * AST];
    __shared__ float sW[64 * AST];

    const bool is_in = (int)blockIdx.x < blocks_in;
    const float* A = is_in ? input : other;
    const float* W = is_in ? Wi : Wo;
    const float* bias = is_in ? bi : nullptr;
    const int M = is_in ? M_in : M_ot;
    const int block_row0 = (is_in ? blockIdx.x : (blockIdx.x - blocks_in)) * 128;
    const int tid = threadIdx.x;

    const int warp = tid >> 5, lane = tid & 31;
    const int g = lane >> 2, tig = lane & 3;
    const int wr = (warp & 1) * 32;
    const int wc = (warp >> 1) * 32;

    stage_W(W, sW, tid);

#pragma unroll
    for (int t = 0; t < 2; t++) {
        const int block_row = block_row0 + t * 64;
        if (block_row >= M) break;
        stage_A(A, block_row, M, sA, tid);
        __syncthreads();

        float cacc[2][4][4] = {};
        tile_mma(sA, sW, wr, wc, g, tig, cacc);

#pragma unroll
        for (int mt = 0; mt < 2; mt++) {
#pragma unroll
            for (int nt = 0; nt < 4; nt++) {
                const int col = wc + nt * 8 + tig * 2;
                float b0 = 0.f, b1 = 0.f;
                if (bias) { b0 = __ldg(bias + col); b1 = __ldg(bias + col + 1); }
                const int row0 = block_row + wr + mt * 16 + g;
                const int row1 = row0 + 8;
                if (is_in) {
                    if (row0 < M)
                        *reinterpret_cast<float2*>(rhs + (size_t)row0 * 64 + col) =
                            make_float2(cacc[mt][nt][0] + b0, cacc[mt][nt][1] + b1);
                    if (row1 < M)
                        *reinterpret_cast<float2*>(rhs + (size_t)row1 * 64 + col) =
                            make_float2(cacc[mt][nt][2] + b0, cacc[mt][nt][3] + b1);
                } else {
                    if (row0 < M)
                        *reinterpret_cast<__half2*>(lhs + (size_t)row0 * 64 + col) =
                            __floats2half2_rn(cacc[mt][nt][0], cacc[mt][nt][1]);
                    if (row1 < M)
                        *reinterpret_cast<__half2*>(lhs + (size_t)row1 * 64 + col) =
                            __floats2half2_rn(cacc[mt][nt][2], cacc[mt][nt][3]);
                }
            }
        }
        __syncthreads();
    }
}

// ============ row accumulate: fp16 lhs gather (R12 delta) ===================
__device__ __forceinline__ float lrelu(float x) {
    return fmaxf(x, 0.f) + 0.01f * fminf(x, 0.f);
}

__global__ void row_kernel(const float* __restrict__ rhs,
                           const __half* __restrict__ lhs,
                           const int* __restrict__ row_start,
                           const float2* __restrict__ edges,
                           const float* __restrict__ We,
                           float* __restrict__ acc, int N) {
    const int row = blockIdx.x * (blockDim.x >> 5) + (threadIdx.x >> 5);
    if (row >= N) return;
    const int lane = threadIdx.x & 31;

    const float2*  rhs2 = reinterpret_cast<const float2*>(rhs);
    const __half2* lhsh = reinterpret_cast<const __half2*>(lhs);
    const float2*  We2  = reinterpret_cast<const float2*>(We);

    const float2 r  = __ldg(rhs2 + (size_t)row * 32 + lane);
    const float2 we = __ldg(We2 + lane);

    const int s = __ldg(row_start + row);
    const int t = __ldg(row_start + row + 1);

    float ax = 0.f, ay = 0.f, bx = 0.f, by = 0.f;
    int j = s;
#pragma unroll 2
    for (; j + 2 <= t; j += 2) {
        float2 e0 = __ldg(edges + j);
        float2 e1 = __ldg(edges + j + 1);
        int l0 = __float_as_int(e0.x);
        int l1 = __float_as_int(e1.x);
        float2 v0 = __half22float2(__ldg(lhsh + (size_t)l0 * 32 + lane));
        float2 v1 = __half22float2(__ldg(lhsh + (size_t)l1 * 32 + lane));
        ax += lrelu(fmaf(e0.y, we.x, r.x + v0.x));
        ay += lrelu(fmaf(e0.y, we.y, r.y + v0.y));
        bx += lrelu(fmaf(e1.y, we.x, r.x + v1.x));
        by += lrelu(fmaf(e1.y, we.y, r.y + v1.y));
    }
    if (j < t) {
        float2 e0 = __ldg(edges + j);
        int l0 = __float_as_int(e0.x);
        float2 v0 = __half22float2(__ldg(lhsh + (size_t)l0 * 32 + lane));
        ax += lrelu(fmaf(e0.y, we.x, r.x + v0.x));
        ay += lrelu(fmaf(e0.y, we.y, r.y + v0.y));
    }
    reinterpret_cast<float2*>(acc)[(size_t)row * 32 + lane] =
        make_float2(ax + bx, ay + by);
}

// ============ precompute ====================================================
__global__ void precompute_kernel(const float* __restrict__ Wf,
                                  const float* __restrict__ bf,
                                  const float* __restrict__ Wout,
                                  float* __restrict__ Wcomb,
                                  float* __restrict__ bfw) {
    int tid = blockIdx.x * blockDim.x + threadIdx.x;
    if (tid < 64 * 64) {
        int k = tid >> 6, d = tid & 63;
        float s0 = 0.f, s1 = 0.f, s2 = 0.f, s3 = 0.f;
#pragma unroll
        for (int j = 0; j < 64; j += 4) {
            s0 = fmaf(__ldg(Wf + k * 64 + j + 0), __ldg(Wout + (j + 0) * 64 + d), s0);
            s1 = fmaf(__ldg(Wf + k * 64 + j + 1), __ldg(Wout + (j + 1) * 64 + d), s1);
            s2 = fmaf(__ldg(Wf + k * 64 + j + 2), __ldg(Wout + (j + 2) * 64 + d), s2);
            s3 = fmaf(__ldg(Wf + k * 64 + j + 3), __ldg(Wout + (j + 3) * 64 + d), s3);
        }
        Wcomb[tid] = (s0 + s1) + (s2 + s3);
    }
    if (tid < 64) {
        float s0 = 0.f, s1 = 0.f;
#pragma unroll
        for (int j = 0; j < 64; j += 2) {
            s0 = fmaf(__ldg(bf + j + 0), __ldg(Wout + (j + 0) * 64 + tid), s0);
            s1 = fmaf(__ldg(bf + j + 1), __ldg(Wout + (j + 1) * 64 + tid), s1);
        }
        bfw[tid] = s0 + s1;
    }
}

// ============ final epilogue ================================================
__global__ __launch_bounds__(128)
void final_tf32(const float* __restrict__ accm,
                const float* __restrict__ input,
                const int* __restrict__ row_start,
                const float* __restrict__ Wcomb,
                const float* __restrict__ WoutB,
                const float* __restrict__ bfw,
                const float* __restrict__ bout,
                float* __restrict__ out, int M) {
    __shared__ float sA[64 * AST];
    __shared__ float sW[64 * AST];
    __shared__ float scnt[64];

    const int block_row = blockIdx.x * 64;
    const int tid = threadIdx.x;

    if (tid < 64) {
        int gr = block_row + tid;
        scnt[tid] = (gr < M)
            ? (float)(__ldg(row_start + gr + 1) - __ldg(row_start + gr)) : 0.f;
    }

    const int warp = tid >> 5, lane = tid & 31;
    const int g = lane >> 2, tig = lane & 3;
    const int wr = (warp & 1) * 32;
    const int wc = (warp >> 1) * 32;

    float cacc[2][4][4] = {};

#pragma unroll
    for (int p = 0; p < 2; p++) {
        const float* Ap = (p == 0) ? accm : input;
        const float* Wp = (p == 0) ? Wcomb : WoutB;
        stage_A(Ap, block_row, M, sA, tid);
        stage_W(Wp, sW, tid);
        __syncthreads();
        tile_mma(sA, sW, wr, wc, g, tig, cacc);
        __syncthreads();
    }

#pragma unroll
    for (int mt = 0; mt < 2; mt++) {
#pragma unroll
        for (int nt = 0; nt < 4; nt++) {
            const int col = wc + nt * 8 + tig * 2;
            const float f0 = __ldg(bfw + col), f1 = __ldg(bfw + col + 1);
            const float o0 = __ldg(bout + col), o1 = __ldg(bout + col + 1);
            const int r0 = wr + mt * 16 + g;
            const int row0 = block_row + r0;
            if (row0 < M) {
                float c = scnt[r0];
                *reinterpret_cast<float2*>(out + (size_t)row0 * 64 + col) =
                    make_float2(cacc[mt][nt][0] + c * f0 + o0,
                                cacc[mt][nt][1] + c * f1 + o1);
            }
            const int row1 = row0 + 8;
            if (row1 < M) {
                float c = scnt[r0 + 8];
                *reinterpret_cast<float2*>(out + (size_t)row1 * 64 + col) =
                    make_float2(cacc[mt][nt][2] + c * f0 + o0,
                                cacc[mt][nt][3] + c * f1 + o1);
            }
        }
    }
}

// ---------------------------------------------------------------------------
extern "C" void kernel_launch(void* const* d_in, const int* in_sizes, int n_in,
                              void* d_out, int out_size) {
    const float* input   = (const float*)d_in[0];
    const float* other   = (const float*)d_in[1];
    const int*   rj      = (const int*)d_in[2];
    const int*   lj      = (const int*)d_in[3];
    const float* weights = (const float*)d_in[4];
    const float* Wi      = (const float*)d_in[5];
    const float* bi      = (const float*)d_in[6];
    const float* Wo      = (const float*)d_in[7];
    const float* We      = (const float*)d_in[8];
    const float* Wf      = (const float*)d_in[9];
    const float* bf      = (const float*)d_in[10];
    const float* Wout    = (const float*)d_in[11];
    const float* bout    = (const float*)d_in[12];
    float* out = (float*)d_out;

    const int N_IN = in_sizes[0] / 64;
    const int N_OT = in_sizes[1] / 64;
    const int E    = in_sizes[2];

    float *rhs, *acc, *Wcomb, *bfw;
    __half* lhs;
    float2* edges;
    int *cnt, *row_start, *cursor, *part;
    cudaGetSymbolAddress((void**)&rhs,       g_rhs);
    cudaGetSymbolAddress((void**)&lhs,       g_lhs);
    cudaGetSymbolAddress((void**)&acc,       g_acc);
    cudaGetSymbolAddress((void**)&cnt,       g_cnt);
    cudaGetSymbolAddress((void**)&row_start, g_row_start);
    cudaGetSymbolAddress((void**)&cursor,    g_cursor);
    cudaGetSymbolAddress((void**)&part,      g_part);
    cudaGetSymbolAddress((void**)&edges,     g_edges);
    cudaGetSymbolAddress((void**)&Wcomb,     g_Wcomb);
    cudaGetSymbolAddress((void**)&bfw,       g_bfw);

    const int NB = (N_IN + SCAN_B - 1) / SCAN_B;

    // 1. counting sort of edges by rj
    zero_cnt_kernel<<<(N_IN + 255) / 256, 256>>>(cnt, N_IN);
    hist_kernel<<<(E + 255) / 256, 256>>>(rj, cnt, E);
    scan_fused_kernel<<<NB, SCAN_B>>>(cnt, row_start, cursor, part, N_IN, E);
    scatter_kernel<<<(E + 1023) / 1024, 256>>>(rj, lj, weights, cursor, part, edges, E);

    // 2. fused input-side GEMMs (lhs emitted as fp16)
    {
        int blocks_in = (N_IN + 127) / 128;
        int blocks_ot = (N_OT + 127) / 128;
        gemm_both_tf32<<<blocks_in + blocks_ot, 128>>>(
            input, Wi, bi, other, Wo, rhs, lhs, N_IN, N_OT, blocks_in);
    }

    // 3. per-row edge accumulation (fp16 gather)
    row_kernel<<<(N_IN + 7) / 8, 256>>>(rhs, lhs, row_start, edges, We, acc, N_IN);

    // 4. folded epilogue weights
    precompute_kernel<<<16, 256>>>(Wf, bf, Wout, Wcomb, bfw);

    // 5. fused epilogue GEMM
    final_tf32<<<(N_IN + 63) / 64, 128>>>(acc, input, row_start, Wcomb,
                                          Wout + 64 * 64, bfw, bout, out, N_IN);
}

// round 13
// speedup vs baseline: 1.0097x; 1.0097x over previous
#include <cuda_runtime.h>
#include <cuda_bf16.h>
#include <cstdint>

// ---------------------------------------------------------------------------
// BipartiteGConv, CSR + 3xTF32 tensor-core GEMMs.
// Base = R11 (139.3us best, fp32 everywhere). R13 deltas: scatter ILP-8;
// row_kernel unroll-4 (same lane mapping, deeper MLP). fp16 lhs reverted.
// ---------------------------------------------------------------------------

#define N_IN_MAX  100000
#define N_OT_MAX  50000
#define E_MAX     1050000
#define SCAN_B    1024
#define READY_BIT 0x40000000
#define VAL_MASK  0x3FFFFFFF

__device__ float  g_rhs[N_IN_MAX * 64];
__device__ float  g_lhs[N_OT_MAX * 64];
__device__ float  g_acc[N_IN_MAX * 64];
__device__ int    g_cnt[N_IN_MAX];
__device__ int    g_row_start[N_IN_MAX + 1];
__device__ int    g_cursor[N_IN_MAX];
__device__ int    g_part[128];
__device__ float2 g_edges[E_MAX];
__device__ float  g_Wcomb[64 * 64];
__device__ float  g_bfw[64];

// ---------------- zero cnt ----------------
__global__ void zero_cnt_kernel(int* __restrict__ cnt, int n) {
    int i = blockIdx.x * blockDim.x + threadIdx.x;
    if (i < n) cnt[i] = 0;
}

// ---------------- histogram ----------------
__global__ void hist_kernel(const int* __restrict__ rj, int* __restrict__ cnt, int E) {
    int e = blockIdx.x * blockDim.x + threadIdx.x;
    if (e < E) atomicAdd(cnt + __ldg(rj + e), 1);
}

// ---------------- fused single-pass scan (R11-proven) ----------------
__global__ void scan_fused_kernel(const int* __restrict__ cnt,
                                  int* __restrict__ row_start,
                                  int* __restrict__ cursor,
                                  int* __restrict__ part, int N, int E) {
    __shared__ int s[SCAN_B];
    __shared__ int prefix_sh;
    const int tid = threadIdx.x;
    const int b = blockIdx.x;
    const int i = b * SCAN_B + tid;

    int v = (i < N) ? cnt[i] : 0;
    s[tid] = v;
    __syncthreads();
    int x = v;
#pragma unroll
    for (int d = 1; d < SCAN_B; d <<= 1) {
        int t = (tid >= d) ? s[tid - d] : 0;
        __syncthreads();
        x += t;
        s[tid] = x;
        __syncthreads();
    }
    const int total = s[SCAN_B - 1];

    if (tid == 0) atomicExch(&part[b], total | READY_BIT);
    if (tid < 32) {
        int pre = 0;
        for (int p = b - 1 - tid; p >= 0; p -= 32) {
            int w;
            do { w = *(volatile int*)(part + p); } while (!(w & READY_BIT));
            pre += w & VAL_MASK;
        }
#pragma unroll
        for (int d = 16; d > 0; d >>= 1)
            pre += __shfl_xor_sync(0xffffffffu, pre, d);
        if (tid == 0) prefix_sh = pre;
    }
    __syncthreads();

    if (i < N) {
        int e = x - v + prefix_sh;
        row_start[i] = e;
        cursor[i] = e;
    }
    if (b == 0 && tid == 0) row_start[N] = E;
}

// ---------------- scatter: ILP-8 (R13 delta #1) ----------------
__global__ void scatter_kernel(const int* __restrict__ rj,
                               const int* __restrict__ lj,
                               const float* __restrict__ w,
                               int* __restrict__ cursor,
                               int* __restrict__ part,
                               float2* __restrict__ edges, int E) {
    if (blockIdx.x == 0 && threadIdx.x < 128) part[threadIdx.x] = 0;
    int base = blockIdx.x * (blockDim.x * 8) + threadIdx.x;
    int   r[8], l[8];
    float wv[8];
    bool  ok[8];
#pragma unroll
    for (int k = 0; k < 8; k++) {
        int e = base + k * 256;
        ok[k] = (e < E);
        if (ok[k]) {
            r[k]  = __ldg(rj + e);
            l[k]  = __ldg(lj + e);
            wv[k] = __ldg(w + e);
        }
    }
    int p[8];
#pragma unroll
    for (int k = 0; k < 8; k++)
        if (ok[k]) p[k] = atomicAdd(cursor + r[k], 1);
#pragma unroll
    for (int k = 0; k < 8; k++)
        if (ok[k]) edges[p[k]] = make_float2(__int_as_float(l[k]), wv[k]);
}

// ======================= tf32 mma helpers ===================================
__device__ __forceinline__ uint32_t cvt_tf32(float x) {
    uint32_t u;
    asm("cvt.rna.tf32.f32 %0, %1;" : "=r"(u) : "f"(x));
    return u;
}
__device__ __forceinline__ void split_tf32(float x, uint32_t& hi, uint32_t& lo) {
    hi = cvt_tf32(x);
    lo = cvt_tf32(x - __uint_as_float(hi));
}
__device__ __forceinline__ void mma8(float* c,
                                     uint32_t a0, uint32_t a1, uint32_t a2, uint32_t a3,
                                     uint32_t b0, uint32_t b1) {
    asm volatile(
        "mma.sync.aligned.m16n8k8.row.col.f32.tf32.tf32.f32 "
        "{%0,%1,%2,%3}, {%4,%5,%6,%7}, {%8,%9}, {%0,%1,%2,%3};"
        : "+f"(c[0]), "+f"(c[1]), "+f"(c[2]), "+f"(c[3])
        : "r"(a0), "r"(a1), "r"(a2), "r"(a3), "r"(b0), "r"(b1));
}

#define AST 68

__device__ __forceinline__ void stage_A(const float* __restrict__ A,
                                        int block_row, int M,
                                        float* sA, int tid) {
#pragma unroll
    for (int it = 0; it < 8; it++) {
        int i = tid + it * 128;
        int r = i >> 4, c4 = (i & 15) * 4;
        int gr = block_row + r;
        float4 v = (gr < M) ? *reinterpret_cast<const float4*>(A + (size_t)gr * 64 + c4)
                            : make_float4(0.f, 0.f, 0.f, 0.f);
        *reinterpret_cast<float4*>(sA + r * AST + c4) = v;
    }
}
__device__ __forceinline__ void stage_W(const float* __restrict__ W,
                                        float* sW, int tid) {
#pragma unroll
    for (int it = 0; it < 8; it++) {
        int i = tid + it * 128;
        int r = i >> 4, c4 = (i & 15) * 4;
        float4 w = *reinterpret_cast<const float4*>(W + r * 64 + c4);
        *reinterpret_cast<float4*>(sW + r * AST + c4) = w;
    }
}

__device__ __forceinline__ void tile_mma(const float* sA, const float* sW,
                                         int wr, int wc, int g, int tig,
                                         float cacc[2][4][4]) {
#pragma unroll
    for (int ks = 0; ks < 8; ks++) {
        const int kb = ks * 8;
        uint32_t ahi[2][4], alo[2][4];
#pragma unroll
        for (int mt = 0; mt < 2; mt++) {
            const int base = (wr + mt * 16 + g) * AST + kb + tig;
            split_tf32(sA[base],               ahi[mt][0], alo[mt][0]);
            split_tf32(sA[base + 8 * AST],     ahi[mt][1], alo[mt][1]);
            split_tf32(sA[base + 4],           ahi[mt][2], alo[mt][2]);
            split_tf32(sA[base + 8 * AST + 4], ahi[mt][3], alo[mt][3]);
        }
#pragma unroll
        for (int nt = 0; nt < 4; nt++) {
            const int nb = wc + nt * 8;
            float w0 = sW[(kb + tig) * AST + nb + g];
            float w1 = sW[(kb + tig + 4) * AST + nb + g];
            uint32_t bh0, bl0, bh1, bl1;
            split_tf32(w0, bh0, bl0);
            split_tf32(w1, bh1, bl1);
#pragma unroll
            for (int mt = 0; mt < 2; mt++) {
                mma8(cacc[mt][nt], ahi[mt][0], ahi[mt][1], ahi[mt][2], ahi[mt][3], bh0, bh1);
                mma8(cacc[mt][nt], ahi[mt][0], ahi[mt][1], ahi[mt][2], ahi[mt][3], bl0, bl1);
                mma8(cacc[mt][nt], alo[mt][0], alo[mt][1], alo[mt][2], alo[mt][3], bh0, bh1);
            }
        }
    }
}

// ============ gemm_both (R11 exact) =========================================
__global__ __launch_bounds__(128)
void gemm_both_tf32(const float* __restrict__ input,
                    const float* __restrict__ Wi,
                    const float* __restrict__ bi,
                    const float* __restrict__ other,
                    const float* __restrict__ Wo,
                    float* __restrict__ rhs,
                    float* __restrict__ lhs,
                    int M_in, int M_ot, int blocks_in) {
    __shared__ float sA[64 * AST];
    __shared__ float sW[64 * AST];

    const bool is_in = (int)blockIdx.x < blocks_in;
    const float* A = is_in ? input : other;
    const float* W = is_in ? Wi : Wo;
    const float* bias = is_in ? bi : nullptr;
    float* C = is_in ? rhs : lhs;
    const int M = is_in ? M_in : M_ot;
    const int block_row0 = (is_in ? blockIdx.x : (blockIdx.x - blocks_in)) * 128;
    const int tid = threadIdx.x;

    const int warp = tid >> 5, lane = tid & 31;
    const int g = lane >> 2, tig = lane & 3;
    const int wr = (warp & 1) * 32;
    const int wc = (warp >> 1) * 32;

    stage_W(W, sW, tid);

#pragma unroll
    for (int t = 0; t < 2; t++) {
        const int block_row = block_row0 + t * 64;
        if (block_row >= M) break;
        stage_A(A, block_row, M, sA, tid);
        __syncthreads();

        float cacc[2][4][4] = {};
        tile_mma(sA, sW, wr, wc, g, tig, cacc);

#pragma unroll
        for (int mt = 0; mt < 2; mt++) {
#pragma unroll
            for (int nt = 0; nt < 4; nt++) {
                const int col = wc + nt * 8 + tig * 2;
                float b0 = 0.f, b1 = 0.f;
                if (bias) { b0 = __ldg(bias + col); b1 = __ldg(bias + col + 1); }
                const int row0 = block_row + wr + mt * 16 + g;
                if (row0 < M)
                    *reinterpret_cast<float2*>(C + (size_t)row0 * 64 + col) =
                        make_float2(cacc[mt][nt][0] + b0, cacc[mt][nt][1] + b1);
                const int row1 = row0 + 8;
                if (row1 < M)
                    *reinterpret_cast<float2*>(C + (size_t)row1 * 64 + col) =
                        make_float2(cacc[mt][nt][2] + b0, cacc[mt][nt][3] + b1);
            }
        }
        __syncthreads();
    }
}

// ============ row accumulate: unroll-4, same lane mapping (R13 delta #2) ====
__device__ __forceinline__ float lrelu(float x) {
    return fmaxf(x, 0.f) + 0.01f * fminf(x, 0.f);
}

__global__ void row_kernel(const float* __restrict__ rhs,
                           const float* __restrict__ lhs,
                           const int* __restrict__ row_start,
                           const float2* __restrict__ edges,
                           const float* __restrict__ We,
                           float* __restrict__ acc, int N) {
    const int row = blockIdx.x * (blockDim.x >> 5) + (threadIdx.x >> 5);
    if (row >= N) return;
    const int lane = threadIdx.x & 31;

    const float2* rhs2 = reinterpret_cast<const float2*>(rhs);
    const float2* lhs2 = reinterpret_cast<const float2*>(lhs);
    const float2* We2  = reinterpret_cast<const float2*>(We);

    const float2 r  = __ldg(rhs2 + (size_t)row * 32 + lane);
    const float2 we = __ldg(We2 + lane);

    const int s = __ldg(row_start + row);
    const int t = __ldg(row_start + row + 1);

    float a0x = 0.f, a0y = 0.f, a1x = 0.f, a1y = 0.f;
    float a2x = 0.f, a2y = 0.f, a3x = 0.f, a3y = 0.f;
    int j = s;
    for (; j + 4 <= t; j += 4) {
        float2 e0 = __ldg(edges + j);
        float2 e1 = __ldg(edges + j + 1);
        float2 e2 = __ldg(edges + j + 2);
        float2 e3 = __ldg(edges + j + 3);
        int l0 = __float_as_int(e0.x);
        int l1 = __float_as_int(e1.x);
        int l2 = __float_as_int(e2.x);
        int l3 = __float_as_int(e3.x);
        float2 v0 = __ldg(lhs2 + (size_t)l0 * 32 + lane);
        float2 v1 = __ldg(lhs2 + (size_t)l1 * 32 + lane);
        float2 v2 = __ldg(lhs2 + (size_t)l2 * 32 + lane);
        float2 v3 = __ldg(lhs2 + (size_t)l3 * 32 + lane);
        a0x += lrelu(fmaf(e0.y, we.x, r.x + v0.x));
        a0y += lrelu(fmaf(e0.y, we.y, r.y + v0.y));
        a1x += lrelu(fmaf(e1.y, we.x, r.x + v1.x));
        a1y += lrelu(fmaf(e1.y, we.y, r.y + v1.y));
        a2x += lrelu(fmaf(e2.y, we.x, r.x + v2.x));
        a2y += lrelu(fmaf(e2.y, we.y, r.y + v2.y));
        a3x += lrelu(fmaf(e3.y, we.x, r.x + v3.x));
        a3y += lrelu(fmaf(e3.y, we.y, r.y + v3.y));
    }
    for (; j < t; j++) {
        float2 e0 = __ldg(edges + j);
        int l0 = __float_as_int(e0.x);
        float2 v0 = __ldg(lhs2 + (size_t)l0 * 32 + lane);
        a0x += lrelu(fmaf(e0.y, we.x, r.x + v0.x));
        a0y += lrelu(fmaf(e0.y, we.y, r.y + v0.y));
    }
    reinterpret_cast<float2*>(acc)[(size_t)row * 32 + lane] =
        make_float2((a0x + a1x) + (a2x + a3x), (a0y + a1y) + (a2y + a3y));
}

// ============ precompute (R11 exact) ========================================
__global__ void precompute_kernel(const float* __restrict__ Wf,
                                  const float* __restrict__ bf,
                                  const float* __restrict__ Wout,
                                  float* __restrict__ Wcomb,
                                  float* __restrict__ bfw) {
    int tid = blockIdx.x * blockDim.x + threadIdx.x;
    if (tid < 64 * 64) {
        int k = tid >> 6, d = tid & 63;
        float s0 = 0.f, s1 = 0.f, s2 = 0.f, s3 = 0.f;
#pragma unroll
        for (int j = 0; j < 64; j += 4) {
            s0 = fmaf(__ldg(Wf + k * 64 + j + 0), __ldg(Wout + (j + 0) * 64 + d), s0);
            s1 = fmaf(__ldg(Wf + k * 64 + j + 1), __ldg(Wout + (j + 1) * 64 + d), s1);
            s2 = fmaf(__ldg(Wf + k * 64 + j + 2), __ldg(Wout + (j + 2) * 64 + d), s2);
            s3 = fmaf(__ldg(Wf + k * 64 + j + 3), __ldg(Wout + (j + 3) * 64 + d), s3);
        }
        Wcomb[tid] = (s0 + s1) + (s2 + s3);
    }
    if (tid < 64) {
        float s0 = 0.f, s1 = 0.f;
#pragma unroll
        for (int j = 0; j < 64; j += 2) {
            s0 = fmaf(__ldg(bf + j + 0), __ldg(Wout + (j + 0) * 64 + tid), s0);
            s1 = fmaf(__ldg(bf + j + 1), __ldg(Wout + (j + 1) * 64 + tid), s1);
        }
        bfw[tid] = s0 + s1;
    }
}

// ============ final epilogue (R11 exact) ====================================
__global__ __launch_bounds__(128)
void final_tf32(const float* __restrict__ accm,
                const float* __restrict__ input,
                const int* __restrict__ row_start,
                const float* __restrict__ Wcomb,
                const float* __restrict__ WoutB,
                const float* __restrict__ bfw,
                const float* __restrict__ bout,
                float* __restrict__ out, int M) {
    __shared__ float sA[64 * AST];
    __shared__ float sW[64 * AST];
    __shared__ float scnt[64];

    const int block_row = blockIdx.x * 64;
    const int tid = threadIdx.x;

    if (tid < 64) {
        int gr = block_row + tid;
        scnt[tid] = (gr < M)
            ? (float)(__ldg(row_start + gr + 1) - __ldg(row_start + gr)) : 0.f;
    }

    const int warp = tid >> 5, lane = tid & 31;
    const int g = lane >> 2, tig = lane & 3;
    const int wr = (warp & 1) * 32;
    const int wc = (warp >> 1) * 32;

    float cacc[2][4][4] = {};

#pragma unroll
    for (int p = 0; p < 2; p++) {
        const float* Ap = (p == 0) ? accm : input;
        const float* Wp = (p == 0) ? Wcomb : WoutB;
        stage_A(Ap, block_row, M, sA, tid);
        stage_W(Wp, sW, tid);
        __syncthreads();
        tile_mma(sA, sW, wr, wc, g, tig, cacc);
        __syncthreads();
    }

#pragma unroll
    for (int mt = 0; mt < 2; mt++) {
#pragma unroll
        for (int nt = 0; nt < 4; nt++) {
            const int col = wc + nt * 8 + tig * 2;
            const float f0 = __ldg(bfw + col), f1 = __ldg(bfw + col + 1);
            const float o0 = __ldg(bout + col), o1 = __ldg(bout + col + 1);
            const int r0 = wr + mt * 16 + g;
            const int row0 = block_row + r0;
            if (row0 < M) {
                float c = scnt[r0];
                *reinterpret_cast<float2*>(out + (size_t)row0 * 64 + col) =
                    make_float2(cacc[mt][nt][0] + c * f0 + o0,
                                cacc[mt][nt][1] + c * f1 + o1);
            }
            const int row1 = row0 + 8;
            if (row1 < M) {
                float c = scnt[r0 + 8];
                *reinterpret_cast<float2*>(out + (size_t)row1 * 64 + col) =
                    make_float2(cacc[mt][nt][2] + c * f0 + o0,
                                cacc[mt][nt][3] + c * f1 + o1);
            }
        }
    }
}

// ---------------------------------------------------------------------------
extern "C" void kernel_launch(void* const* d_in, const int* in_sizes, int n_in,
                              void* d_out, int out_size) {
    const float* input   = (const float*)d_in[0];
    const float* other   = (const float*)d_in[1];
    const int*   rj      = (const int*)d_in[2];
    const int*   lj      = (const int*)d_in[3];
    const float* weights = (const float*)d_in[4];
    const float* Wi      = (const float*)d_in[5];
    const float* bi      = (const float*)d_in[6];
    const float* Wo      = (const float*)d_in[7];
    const float* We      = (const float*)d_in[8];
    const float* Wf      = (const float*)d_in[9];
    const float* bf      = (const float*)d_in[10];
    const float* Wout    = (const float*)d_in[11];
    const float* bout    = (const float*)d_in[12];
    float* out = (float*)d_out;

    const int N_IN = in_sizes[0] / 64;
    const int N_OT = in_sizes[1] / 64;
    const int E    = in_sizes[2];

    float *rhs, *lhs, *acc, *Wcomb, *bfw;
    float2* edges;
    int *cnt, *row_start, *cursor, *part;
    cudaGetSymbolAddress((void**)&rhs,       g_rhs);
    cudaGetSymbolAddress((void**)&lhs,       g_lhs);
    cudaGetSymbolAddress((void**)&acc,       g_acc);
    cudaGetSymbolAddress((void**)&cnt,       g_cnt);
    cudaGetSymbolAddress((void**)&row_start, g_row_start);
    cudaGetSymbolAddress((void**)&cursor,    g_cursor);
    cudaGetSymbolAddress((void**)&part,      g_part);
    cudaGetSymbolAddress((void**)&edges,     g_edges);
    cudaGetSymbolAddress((void**)&Wcomb,     g_Wcomb);
    cudaGetSymbolAddress((void**)&bfw,       g_bfw);

    const int NB = (N_IN + SCAN_B - 1) / SCAN_B;

    // 1. counting sort of edges by rj
    zero_cnt_kernel<<<(N_IN + 255) / 256, 256>>>(cnt, N_IN);
    hist_kernel<<<(E + 255) / 256, 256>>>(rj, cnt, E);
    scan_fused_kernel<<<NB, SCAN_B>>>(cnt, row_start, cursor, part, N_IN, E);
    scatter_kernel<<<(E + 2047) / 2048, 256>>>(rj, lj, weights, cursor, part, edges, E);

    // 2. fused input-side GEMMs
    {
        int blocks_in = (N_IN + 127) / 128;
        int blocks_ot = (N_OT + 127) / 128;
        gemm_both_tf32<<<blocks_in + blocks_ot, 128>>>(
            input, Wi, bi, other, Wo, rhs, lhs, N_IN, N_OT, blocks_in);
    }

    // 3. per-row edge accumulation (unroll-4)
    row_kernel<<<(N_IN + 7) / 8, 256>>>(rhs, lhs, row_start, edges, We, acc, N_IN);

    // 4. folded epilogue weights
    precompute_kernel<<<16, 256>>>(Wf, bf, Wout, Wcomb, bfw);

    // 5. fused epilogue GEMM
    final_tf32<<<(N_IN + 63) / 64, 128>>>(acc, input, row_start, Wcomb,
                                          Wout + 64 * 64, bfw, bout, out, N_IN);
}

// round 14
// speedup vs baseline: 1.0178x; 1.0079x over previous
#include <cuda_runtime.h>
#include <cuda_bf16.h>
#include <cstdint>

// ---------------------------------------------------------------------------
// BipartiteGConv, CSR + 3xTF32 tensor-core GEMMs. 6-launch pipeline:
//   1 hist(+precompute tail blocks)   2 scan (single-pass lookback, zeroes cnt)
//   3 scatter (ILP-4, resets scan flags)   4 gemm_both   5 row (unroll-4)
//   6 final
// Replay-safe: cnt zeroed by scan after read; part[] zeroed by scatter.
// ---------------------------------------------------------------------------

#define N_IN_MAX  100000
#define N_OT_MAX  50000
#define E_MAX     1050000
#define SCAN_B    1024
#define READY_BIT 0x40000000
#define VAL_MASK  0x3FFFFFFF

__device__ float  g_rhs[N_IN_MAX * 64];
__device__ float  g_lhs[N_OT_MAX * 64];
__device__ float  g_acc[N_IN_MAX * 64];
__device__ int    g_cnt[N_IN_MAX];          // BSS-zero; re-zeroed by scan
__device__ int    g_row_start[N_IN_MAX + 1];
__device__ int    g_cursor[N_IN_MAX];
__device__ int    g_part[128];              // lookback slots; reset by scatter
__device__ float2 g_edges[E_MAX];
__device__ float  g_Wcomb[64 * 64];
__device__ float  g_bfw[64];

// ============ 1. histogram + precompute tail ================================
// blocks [0, hist_blocks): histogram. blocks [hist_blocks, hist_blocks+16):
// Wcomb = Wf@Wout[0:64,:], bfw = bf@Wout[0:64,:]  (256 threads each).
__global__ void hist_kernel(const int* __restrict__ rj, int* __restrict__ cnt,
                            int E, int hist_blocks,
                            const float* __restrict__ Wf,
                            const float* __restrict__ bf,
                            const float* __restrict__ Wout,
                            float* __restrict__ Wcomb,
                            float* __restrict__ bfw) {
    if ((int)blockIdx.x < hist_blocks) {
        int e = blockIdx.x * blockDim.x + threadIdx.x;
        if (e < E) atomicAdd(cnt + __ldg(rj + e), 1);
        return;
    }
    // precompute tail
    int tid = (blockIdx.x - hist_blocks) * blockDim.x + threadIdx.x;
    if (tid < 64 * 64) {
        int k = tid >> 6, d = tid & 63;
        float s0 = 0.f, s1 = 0.f, s2 = 0.f, s3 = 0.f;
#pragma unroll
        for (int j = 0; j < 64; j += 4) {
            s0 = fmaf(__ldg(Wf + k * 64 + j + 0), __ldg(Wout + (j + 0) * 64 + d), s0);
            s1 = fmaf(__ldg(Wf + k * 64 + j + 1), __ldg(Wout + (j + 1) * 64 + d), s1);
            s2 = fmaf(__ldg(Wf + k * 64 + j + 2), __ldg(Wout + (j + 2) * 64 + d), s2);
            s3 = fmaf(__ldg(Wf + k * 64 + j + 3), __ldg(Wout + (j + 3) * 64 + d), s3);
        }
        Wcomb[tid] = (s0 + s1) + (s2 + s3);
    }
    if (tid < 64) {
        float s0 = 0.f, s1 = 0.f;
#pragma unroll
        for (int j = 0; j < 64; j += 2) {
            s0 = fmaf(__ldg(bf + j + 0), __ldg(Wout + (j + 0) * 64 + tid), s0);
            s1 = fmaf(__ldg(bf + j + 1), __ldg(Wout + (j + 1) * 64 + tid), s1);
        }
        bfw[tid] = s0 + s1;
    }
}

// ============ 2. single-pass scan; zeroes cnt after read ====================
__global__ void scan_fused_kernel(int* __restrict__ cnt,
                                  int* __restrict__ row_start,
                                  int* __restrict__ cursor,
                                  int* __restrict__ part, int N, int E) {
    __shared__ int s[SCAN_B];
    __shared__ int prefix_sh;
    const int tid = threadIdx.x;
    const int b = blockIdx.x;
    const int i = b * SCAN_B + tid;

    int v = 0;
    if (i < N) {
        v = cnt[i];
        cnt[i] = 0;          // reset for the next graph replay
    }
    s[tid] = v;
    __syncthreads();
    int x = v;
#pragma unroll
    for (int d = 1; d < SCAN_B; d <<= 1) {
        int t = (tid >= d) ? s[tid - d] : 0;
        __syncthreads();
        x += t;
        s[tid] = x;
        __syncthreads();
    }
    const int total = s[SCAN_B - 1];

    if (tid == 0) atomicExch(&part[b], total | READY_BIT);
    if (tid < 32) {
        int pre = 0;
        for (int p = b - 1 - tid; p >= 0; p -= 32) {
            int w;
            do { w = *(volatile int*)(part + p); } while (!(w & READY_BIT));
            pre += w & VAL_MASK;
        }
#pragma unroll
        for (int d = 16; d > 0; d >>= 1)
            pre += __shfl_xor_sync(0xffffffffu, pre, d);
        if (tid == 0) prefix_sh = pre;
    }
    __syncthreads();

    if (i < N) {
        int e = x - v + prefix_sh;
        row_start[i] = e;
        cursor[i] = e;
    }
    if (b == 0 && tid == 0) row_start[N] = E;
}

// ============ 3. scatter (ILP-4, R11 form + flag reset) =====================
__global__ void scatter_kernel(const int* __restrict__ rj,
                               const int* __restrict__ lj,
                               const float* __restrict__ w,
                               int* __restrict__ cursor,
                               int* __restrict__ part,
                               float2* __restrict__ edges, int E) {
    if (blockIdx.x == 0 && threadIdx.x < 128) part[threadIdx.x] = 0;
    int base = blockIdx.x * (blockDim.x * 4) + threadIdx.x;
    int   r[4], l[4];
    float wv[4];
    bool  ok[4];
#pragma unroll
    for (int k = 0; k < 4; k++) {
        int e = base + k * 256;
        ok[k] = (e < E);
        if (ok[k]) {
            r[k]  = __ldg(rj + e);
            l[k]  = __ldg(lj + e);
            wv[k] = __ldg(w + e);
        }
    }
    int p[4];
#pragma unroll
    for (int k = 0; k < 4; k++)
        if (ok[k]) p[k] = atomicAdd(cursor + r[k], 1);
#pragma unroll
    for (int k = 0; k < 4; k++)
        if (ok[k]) edges[p[k]] = make_float2(__int_as_float(l[k]), wv[k]);
}

// ======================= tf32 mma helpers ===================================
__device__ __forceinline__ uint32_t cvt_tf32(float x) {
    uint32_t u;
    asm("cvt.rna.tf32.f32 %0, %1;" : "=r"(u) : "f"(x));
    return u;
}
__device__ __forceinline__ void split_tf32(float x, uint32_t& hi, uint32_t& lo) {
    hi = cvt_tf32(x);
    lo = cvt_tf32(x - __uint_as_float(hi));
}
__device__ __forceinline__ void mma8(float* c,
                                     uint32_t a0, uint32_t a1, uint32_t a2, uint32_t a3,
                                     uint32_t b0, uint32_t b1) {
    asm volatile(
        "mma.sync.aligned.m16n8k8.row.col.f32.tf32.tf32.f32 "
        "{%0,%1,%2,%3}, {%4,%5,%6,%7}, {%8,%9}, {%0,%1,%2,%3};"
        : "+f"(c[0]), "+f"(c[1]), "+f"(c[2]), "+f"(c[3])
        : "r"(a0), "r"(a1), "r"(a2), "r"(a3), "r"(b0), "r"(b1));
}

#define AST 68

__device__ __forceinline__ void stage_A(const float* __restrict__ A,
                                        int block_row, int M,
                                        float* sA, int tid) {
#pragma unroll
    for (int it = 0; it < 8; it++) {
        int i = tid + it * 128;
        int r = i >> 4, c4 = (i & 15) * 4;
        int gr = block_row + r;
        float4 v = (gr < M) ? *reinterpret_cast<const float4*>(A + (size_t)gr * 64 + c4)
                            : make_float4(0.f, 0.f, 0.f, 0.f);
        *reinterpret_cast<float4*>(sA + r * AST + c4) = v;
    }
}
__device__ __forceinline__ void stage_W(const float* __restrict__ W,
                                        float* sW, int tid) {
#pragma unroll
    for (int it = 0; it < 8; it++) {
        int i = tid + it * 128;
        int r = i >> 4, c4 = (i & 15) * 4;
        float4 w = *reinterpret_cast<const float4*>(W + r * 64 + c4);
        *reinterpret_cast<float4*>(sW + r * AST + c4) = w;
    }
}

__device__ __forceinline__ void tile_mma(const float* sA, const float* sW,
                                         int wr, int wc, int g, int tig,
                                         float cacc[2][4][4]) {
#pragma unroll
    for (int ks = 0; ks < 8; ks++) {
        const int kb = ks * 8;
        uint32_t ahi[2][4], alo[2][4];
#pragma unroll
        for (int mt = 0; mt < 2; mt++) {
            const int base = (wr + mt * 16 + g) * AST + kb + tig;
            split_tf32(sA[base],               ahi[mt][0], alo[mt][0]);
            split_tf32(sA[base + 8 * AST],     ahi[mt][1], alo[mt][1]);
            split_tf32(sA[base + 4],           ahi[mt][2], alo[mt][2]);
            split_tf32(sA[base + 8 * AST + 4], ahi[mt][3], alo[mt][3]);
        }
#pragma unroll
        for (int nt = 0; nt < 4; nt++) {
            const int nb = wc + nt * 8;
            float w0 = sW[(kb + tig) * AST + nb + g];
            float w1 = sW[(kb + tig + 4) * AST + nb + g];
            uint32_t bh0, bl0, bh1, bl1;
            split_tf32(w0, bh0, bl0);
            split_tf32(w1, bh1, bl1);
#pragma unroll
            for (int mt = 0; mt < 2; mt++) {
                mma8(cacc[mt][nt], ahi[mt][0], ahi[mt][1], ahi[mt][2], ahi[mt][3], bh0, bh1);
                mma8(cacc[mt][nt], ahi[mt][0], ahi[mt][1], ahi[mt][2], ahi[mt][3], bl0, bl1);
                mma8(cacc[mt][nt], alo[mt][0], alo[mt][1], alo[mt][2], alo[mt][3], bh0, bh1);
            }
        }
    }
}

// ============ 4. gemm_both (R11 exact) ======================================
__global__ __launch_bounds__(128)
void gemm_both_tf32(const float* __restrict__ input,
                    const float* __restrict__ Wi,
                    const float* __restrict__ bi,
                    const float* __restrict__ other,
                    const float* __restrict__ Wo,
                    float* __restrict__ rhs,
                    float* __restrict__ lhs,
                    int M_in, int M_ot, int blocks_in) {
    __shared__ float sA[64 * AST];
    __shared__ float sW[64 * AST];

    const bool is_in = (int)blockIdx.x < blocks_in;
    const float* A = is_in ? input : other;
    const float* W = is_in ? Wi : Wo;
    const float* bias = is_in ? bi : nullptr;
    float* C = is_in ? rhs : lhs;
    const int M = is_in ? M_in : M_ot;
    const int block_row0 = (is_in ? blockIdx.x : (blockIdx.x - blocks_in)) * 128;
    const int tid = threadIdx.x;

    const int warp = tid >> 5, lane = tid & 31;
    const int g = lane >> 2, tig = lane & 3;
    const int wr = (warp & 1) * 32;
    const int wc = (warp >> 1) * 32;

    stage_W(W, sW, tid);

#pragma unroll
    for (int t = 0; t < 2; t++) {
        const int block_row = block_row0 + t * 64;
        if (block_row >= M) break;
        stage_A(A, block_row, M, sA, tid);
        __syncthreads();

        float cacc[2][4][4] = {};
        tile_mma(sA, sW, wr, wc, g, tig, cacc);

#pragma unroll
        for (int mt = 0; mt < 2; mt++) {
#pragma unroll
            for (int nt = 0; nt < 4; nt++) {
                const int col = wc + nt * 8 + tig * 2;
                float b0 = 0.f, b1 = 0.f;
                if (bias) { b0 = __ldg(bias + col); b1 = __ldg(bias + col + 1); }
                const int row0 = block_row + wr + mt * 16 + g;
                if (row0 < M)
                    *reinterpret_cast<float2*>(C + (size_t)row0 * 64 + col) =
                        make_float2(cacc[mt][nt][0] + b0, cacc[mt][nt][1] + b1);
                const int row1 = row0 + 8;
                if (row1 < M)
                    *reinterpret_cast<float2*>(C + (size_t)row1 * 64 + col) =
                        make_float2(cacc[mt][nt][2] + b0, cacc[mt][nt][3] + b1);
            }
        }
        __syncthreads();
    }
}

// ============ 5. row accumulate (R13 unroll-4, proven) ======================
__device__ __forceinline__ float lrelu(float x) {
    return fmaxf(x, 0.f) + 0.01f * fminf(x, 0.f);
}

__global__ void row_kernel(const float* __restrict__ rhs,
                           const float* __restrict__ lhs,
                           const int* __restrict__ row_start,
                           const float2* __restrict__ edges,
                           const float* __restrict__ We,
                           float* __restrict__ acc, int N) {
    const int row = blockIdx.x * (blockDim.x >> 5) + (threadIdx.x >> 5);
    if (row >= N) return;
    const int lane = threadIdx.x & 31;

    const float2* rhs2 = reinterpret_cast<const float2*>(rhs);
    const float2* lhs2 = reinterpret_cast<const float2*>(lhs);
    const float2* We2  = reinterpret_cast<const float2*>(We);

    const float2 r  = __ldg(rhs2 + (size_t)row * 32 + lane);
    const float2 we = __ldg(We2 + lane);

    const int s = __ldg(row_start + row);
    const int t = __ldg(row_start + row + 1);

    float a0x = 0.f, a0y = 0.f, a1x = 0.f, a1y = 0.f;
    float a2x = 0.f, a2y = 0.f, a3x = 0.f, a3y = 0.f;
    int j = s;
    for (; j + 4 <= t; j += 4) {
        float2 e0 = __ldg(edges + j);
        float2 e1 = __ldg(edges + j + 1);
        float2 e2 = __ldg(edges + j + 2);
        float2 e3 = __ldg(edges + j + 3);
        int l0 = __float_as_int(e0.x);
        int l1 = __float_as_int(e1.x);
        int l2 = __float_as_int(e2.x);
        int l3 = __float_as_int(e3.x);
        float2 v0 = __ldg(lhs2 + (size_t)l0 * 32 + lane);
        float2 v1 = __ldg(lhs2 + (size_t)l1 * 32 + lane);
        float2 v2 = __ldg(lhs2 + (size_t)l2 * 32 + lane);
        float2 v3 = __ldg(lhs2 + (size_t)l3 * 32 + lane);
        a0x += lrelu(fmaf(e0.y, we.x, r.x + v0.x));
        a0y += lrelu(fmaf(e0.y, we.y, r.y + v0.y));
        a1x += lrelu(fmaf(e1.y, we.x, r.x + v1.x));
        a1y += lrelu(fmaf(e1.y, we.y, r.y + v1.y));
        a2x += lrelu(fmaf(e2.y, we.x, r.x + v2.x));
        a2y += lrelu(fmaf(e2.y, we.y, r.y + v2.y));
        a3x += lrelu(fmaf(e3.y, we.x, r.x + v3.x));
        a3y += lrelu(fmaf(e3.y, we.y, r.y + v3.y));
    }
    for (; j < t; j++) {
        float2 e0 = __ldg(edges + j);
        int l0 = __float_as_int(e0.x);
        float2 v0 = __ldg(lhs2 + (size_t)l0 * 32 + lane);
        a0x += lrelu(fmaf(e0.y, we.x, r.x + v0.x));
        a0y += lrelu(fmaf(e0.y, we.y, r.y + v0.y));
    }
    reinterpret_cast<float2*>(acc)[(size_t)row * 32 + lane] =
        make_float2((a0x + a1x) + (a2x + a3x), (a0y + a1y) + (a2y + a3y));
}

// ============ 6. final epilogue (R11 exact) =================================
__global__ __launch_bounds__(128)
void final_tf32(const float* __restrict__ accm,
                const float* __restrict__ input,
                const int* __restrict__ row_start,
                const float* __restrict__ Wcomb,
                const float* __restrict__ WoutB,
                const float* __restrict__ bfw,
                const float* __restrict__ bout,
                float* __restrict__ out, int M) {
    __shared__ float sA[64 * AST];
    __shared__ float sW[64 * AST];
    __shared__ float scnt[64];

    const int block_row = blockIdx.x * 64;
    const int tid = threadIdx.x;

    if (tid < 64) {
        int gr = block_row + tid;
        scnt[tid] = (gr < M)
            ? (float)(__ldg(row_start + gr + 1) - __ldg(row_start + gr)) : 0.f;
    }

    const int warp = tid >> 5, lane = tid & 31;
    const int g = lane >> 2, tig = lane & 3;
    const int wr = (warp & 1) * 32;
    const int wc = (warp >> 1) * 32;

    float cacc[2][4][4] = {};

#pragma unroll
    for (int p = 0; p < 2; p++) {
        const float* Ap = (p == 0) ? accm : input;
        const float* Wp = (p == 0) ? Wcomb : WoutB;
        stage_A(Ap, block_row, M, sA, tid);
        stage_W(Wp, sW, tid);
        __syncthreads();
        tile_mma(sA, sW, wr, wc, g, tig, cacc);
        __syncthreads();
    }

#pragma unroll
    for (int mt = 0; mt < 2; mt++) {
#pragma unroll
        for (int nt = 0; nt < 4; nt++) {
            const int col = wc + nt * 8 + tig * 2;
            const float f0 = __ldg(bfw + col), f1 = __ldg(bfw + col + 1);
            const float o0 = __ldg(bout + col), o1 = __ldg(bout + col + 1);
            const int r0 = wr + mt * 16 + g;
            const int row0 = block_row + r0;
            if (row0 < M) {
                float c = scnt[r0];
                *reinterpret_cast<float2*>(out + (size_t)row0 * 64 + col) =
                    make_float2(cacc[mt][nt][0] + c * f0 + o0,
                                cacc[mt][nt][1] + c * f1 + o1);
            }
            const int row1 = row0 + 8;
            if (row1 < M) {
                float c = scnt[r0 + 8];
                *reinterpret_cast<float2*>(out + (size_t)row1 * 64 + col) =
                    make_float2(cacc[mt][nt][2] + c * f0 + o0,
                                cacc[mt][nt][3] + c * f1 + o1);
            }
        }
    }
}

// ---------------------------------------------------------------------------
extern "C" void kernel_launch(void* const* d_in, const int* in_sizes, int n_in,
                              void* d_out, int out_size) {
    const float* input   = (const float*)d_in[0];
    const float* other   = (const float*)d_in[1];
    const int*   rj      = (const int*)d_in[2];
    const int*   lj      = (const int*)d_in[3];
    const float* weights = (const float*)d_in[4];
    const float* Wi      = (const float*)d_in[5];
    const float* bi      = (const float*)d_in[6];
    const float* Wo      = (const float*)d_in[7];
    const float* We      = (const float*)d_in[8];
    const float* Wf      = (const float*)d_in[9];
    const float* bf      = (const float*)d_in[10];
    const float* Wout    = (const float*)d_in[11];
    const float* bout    = (const float*)d_in[12];
    float* out = (float*)d_out;

    const int N_IN = in_sizes[0] / 64;
    const int N_OT = in_sizes[1] / 64;
    const int E    = in_sizes[2];

    float *rhs, *lhs, *acc, *Wcomb, *bfw;
    float2* edges;
    int *cnt, *row_start, *cursor, *part;
    cudaGetSymbolAddress((void**)&rhs,       g_rhs);
    cudaGetSymbolAddress((void**)&lhs,       g_lhs);
    cudaGetSymbolAddress((void**)&acc,       g_acc);
    cudaGetSymbolAddress((void**)&cnt,       g_cnt);
    cudaGetSymbolAddress((void**)&row_start, g_row_start);
    cudaGetSymbolAddress((void**)&cursor,    g_cursor);
    cudaGetSymbolAddress((void**)&part,      g_part);
    cudaGetSymbolAddress((void**)&edges,     g_edges);
    cudaGetSymbolAddress((void**)&Wcomb,     g_Wcomb);
    cudaGetSymbolAddress((void**)&bfw,       g_bfw);

    const int NB = (N_IN + SCAN_B - 1) / SCAN_B;   // 98 <= 148 SMs
    const int hist_blocks = (E + 255) / 256;

    // 1. hist (+16 precompute tail blocks)
    hist_kernel<<<hist_blocks + 16, 256>>>(rj, cnt, E, hist_blocks,
                                           Wf, bf, Wout, Wcomb, bfw);

    // 2. single-pass scan (zeroes cnt for next replay)
    scan_fused_kernel<<<NB, SCAN_B>>>(cnt, row_start, cursor, part, N_IN, E);

    // 3. scatter (ILP-4; resets scan flags)
    scatter_kernel<<<(E + 1023) / 1024, 256>>>(rj, lj, weights, cursor, part, edges, E);

    // 4. fused input-side GEMMs
    {
        int blocks_in = (N_IN + 127) / 128;
        int blocks_ot = (N_OT + 127) / 128;
        gemm_both_tf32<<<blocks_in + blocks_ot, 128>>>(
            input, Wi, bi, other, Wo, rhs, lhs, N_IN, N_OT, blocks_in);
    }

    // 5. per-row edge accumulation (unroll-4)
    row_kernel<<<(N_IN + 7) / 8, 256>>>(rhs, lhs, row_start, edges, We, acc, N_IN);

    // 6. fused epilogue GEMM
    final_tf32<<<(N_IN + 63) / 64, 128>>>(acc, input, row_start, Wcomb,
                                          Wout + 64 * 64, bfw, bout, out, N_IN);
}